// round 2
// baseline (speedup 1.0000x reference)
#include <cuda_runtime.h>
#include <math_constants.h>

#define NH    16
#define HD    64
#define SEQ   1024
#define BATCH 4
#define HID   1024

// scratch: Q/K/V in [b, h, s, d] layout (16 MB each)
__device__ float g_Q[BATCH * NH * SEQ * HD];
__device__ float g_K[BATCH * NH * SEQ * HD];
__device__ float g_V[BATCH * NH * SEQ * HD];

// ---------------------------------------------------------------------------
// Kernel 1: fused QKV projection.  C[n,o] = sum_i hs[n,i] * w[o,i] + bias[o]
// M=4096, N=3072, K=1024.  128x128 tile, BK=8, 256 threads, 8x8 microtile.
// Epilogue scatters directly into g_Q/g_K/g_V head layout.
// ---------------------------------------------------------------------------
__global__ __launch_bounds__(256) void qkv_gemm_kernel(
    const float* __restrict__ hs,
    const float* __restrict__ w,
    const float* __restrict__ bias)
{
    __shared__ __align__(16) float As[8][132];
    __shared__ __align__(16) float Bs[8][132];

    const int tid = threadIdx.x;
    const int m0  = blockIdx.y * 128;
    const int n0  = blockIdx.x * 128;
    const int tx  = tid & 15;       // 16 col groups
    const int ty  = tid >> 4;       // 16 row groups
    const int lr  = tid >> 1;       // 0..127 (tile row for loads)
    const int lk  = (tid & 1) * 4;  // 0 or 4 (k offset for loads)

    float acc[8][8];
#pragma unroll
    for (int a = 0; a < 8; a++)
#pragma unroll
        for (int c = 0; c < 8; c++) acc[a][c] = 0.f;

    const float* ga = hs + (size_t)(m0 + lr) * HID + lk;
    const float* gb = w  + (size_t)(n0 + lr) * HID + lk;

    for (int k0 = 0; k0 < HID; k0 += 8) {
        float4 av = *(const float4*)(ga + k0);
        float4 bv = *(const float4*)(gb + k0);
        __syncthreads();
        As[lk + 0][lr] = av.x; As[lk + 1][lr] = av.y;
        As[lk + 2][lr] = av.z; As[lk + 3][lr] = av.w;
        Bs[lk + 0][lr] = bv.x; Bs[lk + 1][lr] = bv.y;
        Bs[lk + 2][lr] = bv.z; Bs[lk + 3][lr] = bv.w;
        __syncthreads();
#pragma unroll
        for (int kk = 0; kk < 8; kk++) {
            float a[8], b[8];
            *(float4*)(a)     = *(const float4*)&As[kk][ty * 8];
            *(float4*)(a + 4) = *(const float4*)&As[kk][ty * 8 + 4];
            *(float4*)(b)     = *(const float4*)&Bs[kk][tx * 4];
            *(float4*)(b + 4) = *(const float4*)&Bs[kk][64 + tx * 4];
#pragma unroll
            for (int i = 0; i < 8; i++)
#pragma unroll
                for (int c = 0; c < 8; c++)
                    acc[i][c] += a[i] * b[c];
        }
    }

    // epilogue: add bias, scatter to Q/K/V [bh][s][d] with coalesced float4
#pragma unroll
    for (int a = 0; a < 8; a++) {
        const int row = m0 + ty * 8 + a;     // hs row = b*1024 + s
        const int bb  = row >> 10;
        const int s   = row & 1023;
#pragma unroll
        for (int g = 0; g < 2; g++) {
            const int o0  = n0 + g * 64 + tx * 4;
            const int t   = o0 >> 10;        // 0=q 1=k 2=v
            const int rem = o0 & 1023;
            const int hh  = rem >> 6;
            const int dd  = rem & 63;
            float* dst = (t == 0) ? g_Q : (t == 1) ? g_K : g_V;
            float4 v;
            v.x = acc[a][g * 4 + 0] + bias[o0 + 0];
            v.y = acc[a][g * 4 + 1] + bias[o0 + 1];
            v.z = acc[a][g * 4 + 2] + bias[o0 + 2];
            v.w = acc[a][g * 4 + 3] + bias[o0 + 3];
            *(float4*)(dst + ((size_t)(bb * NH + hh) * SEQ + s) * HD + dd) = v;
        }
    }
}

// ---------------------------------------------------------------------------
// Kernel 2: attention with relative_key_query bias, flash-style online
// softmax.  One block = one (b,h) x 64 query rows.  128 threads.
// Thread (ti 0..7, tj 0..15): score microtile 8 rows x 4 cols.
// S[i,j] = q_i.k_j + (q_i + k_j) . E[(l-r)+1023]  (E band in smem per r-tile)
// ---------------------------------------------------------------------------
#define QT_STRIDE 68
#define ET_STRIDE 129
#define PS_STRIDE 68
#define ATTN_SMEM_FLOATS (64*QT_STRIDE*2 + 64*ET_STRIDE + 64*64 + 64*PS_STRIDE)

__global__ __launch_bounds__(128) void attn_kernel(
    const float* __restrict__ emb,
    const float* __restrict__ mask,
    float* __restrict__ out)
{
    extern __shared__ __align__(16) float sm[];
    float* Qt = sm;                       // [64 dd][68]: Qt[dd*68 + i]
    float* Kt = Qt + 64 * QT_STRIDE;      // [64 dd][68]: Kt[dd*68 + j]
    float* Et = Kt + 64 * QT_STRIDE;      // [64 dd][129]: Et[dd*129 + ib]
    float* Vs = Et + 64 * ET_STRIDE;      // [64 j][64 dd]
    float* Ps = Vs + 64 * 64;             // [64 i][68]

    const int tid = threadIdx.x;
    const int ti  = tid >> 4;   // 0..7  -> rows i0 = ti*8
    const int tj  = tid & 15;   // 0..15 -> cols j0 = tj*4
    const int bh  = blockIdx.y;
    const int b   = bh >> 4;
    const int hh  = bh & 15;
    const int l0  = blockIdx.x * 64;

    // load Q tile transposed
    const float* Qg = g_Q + ((size_t)bh * SEQ + l0) * HD;
    for (int idx = tid; idx < 64 * 64; idx += 128) {
        const int i = idx >> 6, dd = idx & 63;
        Qt[dd * QT_STRIDE + i] = Qg[idx];
    }

    float mrow[8], lsum[8], acc[8][4];
#pragma unroll
    for (int a = 0; a < 8; a++) {
        mrow[a] = -CUDART_INF_F; lsum[a] = 0.f;
#pragma unroll
        for (int c = 0; c < 4; c++) acc[a][c] = 0.f;
    }

    const int ibase = ti * 8 - tj * 4 + 60;   // band offset: pair (a,c) -> e[a-c+3]

    for (int r0 = 0; r0 < SEQ; r0 += 64) {
        const float* Kg = g_K + ((size_t)bh * SEQ + r0) * HD;
        const float* Vg = g_V + ((size_t)bh * SEQ + r0) * HD;
        const int gb_ = l0 - r0 + 960;  // global emb row = gb_ + ib, ib in [0,127)

        __syncthreads();   // previous PV done before overwriting Kt/Vs/Et
        for (int idx = tid; idx < 64 * 64; idx += 128) {
            const int i = idx >> 6, dd = idx & 63;
            Kt[dd * QT_STRIDE + i] = Kg[idx];
            Vs[idx] = Vg[idx];
        }
        for (int idx = tid; idx < 127 * 64; idx += 128) {
            const int ib = idx >> 6, dd = idx & 63;
            Et[dd * ET_STRIDE + ib] = emb[(size_t)(gb_ + ib) * HD + dd];
        }
        __syncthreads();

        // ---- score tile ----
        float s[8][4];
#pragma unroll
        for (int a = 0; a < 8; a++)
#pragma unroll
            for (int c = 0; c < 4; c++) s[a][c] = 0.f;

#pragma unroll 4
        for (int dd = 0; dd < 64; dd++) {
            float q[8], k[4], e[11];
            const float* qr = &Qt[dd * QT_STRIDE + ti * 8];
            *(float4*)(q)     = *(const float4*)(qr);
            *(float4*)(q + 4) = *(const float4*)(qr + 4);
            *(float4*)(k)     = *(const float4*)&Kt[dd * QT_STRIDE + tj * 4];
            const float* er = &Et[dd * ET_STRIDE + ibase];
#pragma unroll
            for (int u = 0; u < 11; u++) e[u] = er[u];
#pragma unroll
            for (int a = 0; a < 8; a++)
#pragma unroll
                for (int c = 0; c < 4; c++)
                    s[a][c] += q[a] * k[c] + (q[a] + k[c]) * e[a - c + 3];
        }

        // ---- scale + mask ----
        float mk[4];
#pragma unroll
        for (int c = 0; c < 4; c++) mk[c] = mask[b * SEQ + r0 + tj * 4 + c];
#pragma unroll
        for (int a = 0; a < 8; a++)
#pragma unroll
            for (int c = 0; c < 4; c++)
                s[a][c] = s[a][c] * 0.125f + mk[c];

        // ---- online softmax (row reduce over 16 tj threads = half-warp) ----
#pragma unroll
        for (int a = 0; a < 8; a++) {
            float pm = fmaxf(fmaxf(s[a][0], s[a][1]), fmaxf(s[a][2], s[a][3]));
#pragma unroll
            for (int off = 8; off > 0; off >>= 1)
                pm = fmaxf(pm, __shfl_xor_sync(0xffffffffu, pm, off));
            const float mnew = fmaxf(mrow[a], pm);
            const float corr = __expf(mrow[a] - mnew);
            mrow[a] = mnew;
            float p4[4], ps = 0.f;
#pragma unroll
            for (int c = 0; c < 4; c++) { p4[c] = __expf(s[a][c] - mnew); ps += p4[c]; }
#pragma unroll
            for (int off = 8; off > 0; off >>= 1)
                ps += __shfl_xor_sync(0xffffffffu, ps, off);
            lsum[a] = lsum[a] * corr + ps;
#pragma unroll
            for (int c = 0; c < 4; c++) acc[a][c] *= corr;
            *(float4*)&Ps[(ti * 8 + a) * PS_STRIDE + tj * 4] =
                make_float4(p4[0], p4[1], p4[2], p4[3]);
        }
        __syncthreads();

        // ---- P @ V ----
#pragma unroll 2
        for (int j = 0; j < 64; j++) {
            const float4 v4 = *(const float4*)&Vs[j * 64 + tj * 4];
#pragma unroll
            for (int a = 0; a < 8; a++) {
                const float p = Ps[(ti * 8 + a) * PS_STRIDE + j];
                acc[a][0] += p * v4.x; acc[a][1] += p * v4.y;
                acc[a][2] += p * v4.z; acc[a][3] += p * v4.w;
            }
        }
    }

    // ---- write context: out[b, l, hh*64 + d] ----
#pragma unroll
    for (int a = 0; a < 8; a++) {
        const float inv = 1.f / lsum[a];
        const int l = l0 + ti * 8 + a;
        const float4 v = make_float4(acc[a][0] * inv, acc[a][1] * inv,
                                     acc[a][2] * inv, acc[a][3] * inv);
        *(float4*)(out + (size_t)(b * SEQ + l) * HID + hh * HD + tj * 4) = v;
    }
}

// ---------------------------------------------------------------------------
extern "C" void kernel_launch(void* const* d_in, const int* in_sizes, int n_in,
                              void* d_out, int out_size)
{
    (void)in_sizes; (void)n_in; (void)out_size;
    const float* hs   = (const float*)d_in[0];
    const float* w    = (const float*)d_in[1];
    const float* bias = (const float*)d_in[2];
    const float* emb  = (const float*)d_in[3];
    const float* mask = (const float*)d_in[4];
    float* out = (float*)d_out;

    qkv_gemm_kernel<<<dim3(HID * 3 / 128, BATCH * SEQ / 128), 256>>>(hs, w, bias);

    const size_t smem = (size_t)ATTN_SMEM_FLOATS * sizeof(float);
    cudaFuncSetAttribute(attn_kernel,
                         cudaFuncAttributeMaxDynamicSharedMemorySize, (int)smem);
    attn_kernel<<<dim3(SEQ / 64, BATCH * NH), 128, smem>>>(emb, mask, out);
}

// round 4
// speedup vs baseline: 1.2931x; 1.2931x over previous
#include <cuda_runtime.h>
#include <math_constants.h>
#include <cstdint>

#define NH    16
#define HD    64
#define SEQ   1024
#define BATCH 4
#define HID   1024

// scratch: Q/K/V in [b, h, s, d] layout (16 MB each)
__device__ float g_Q[BATCH * NH * SEQ * HD];
__device__ float g_K[BATCH * NH * SEQ * HD];
__device__ float g_V[BATCH * NH * SEQ * HD];

// ===========================================================================
// Kernel 1: fused QKV projection via mma.sync tf32 (legacy HMMA path — the
// only tensor path that compiles under the harness's non-'a' PTX target).
// C[4096, 3072] = hs[4096,1024] x w[3072,1024]^T + bias
// Block 128x128, BK=32, 8 warps, warp tile 64x32 (4x4 m16n8k8), double-buffered
// smem with stride-36 padding (conflict-free fragment loads: bank = 4g + t).
// ===========================================================================
#define SST 36                       // smem row stride in floats
#define QG_BUF_FLOATS (128 * SST)    // one 128x32 tile (padded)
#define QG_SMEM_B (4 * QG_BUF_FLOATS * 4)  // A0/A1/B0/B1

__device__ __forceinline__ float tf32r(float x) {
    uint32_t u;
    asm("cvt.rna.tf32.f32 %0, %1;" : "=r"(u) : "f"(x));
    return __uint_as_float(u);
}

__device__ __forceinline__ void mma16n8k8(float c[4], const uint32_t a[4],
                                          const uint32_t b[2]) {
    asm volatile(
        "mma.sync.aligned.m16n8k8.row.col.f32.tf32.tf32.f32 "
        "{%0,%1,%2,%3}, {%4,%5,%6,%7}, {%8,%9}, {%0,%1,%2,%3};"
        : "+f"(c[0]), "+f"(c[1]), "+f"(c[2]), "+f"(c[3])
        : "r"(a[0]), "r"(a[1]), "r"(a[2]), "r"(a[3]), "r"(b[0]), "r"(b[1]));
}

__global__ __launch_bounds__(256) void qkv_gemm_mma(
    const float* __restrict__ hs,
    const float* __restrict__ w,
    const float* __restrict__ bias)
{
    extern __shared__ __align__(16) float sm[];
    float* As = sm;                        // [2][128][SST]
    float* Bs = sm + 2 * QG_BUF_FLOATS;    // [2][128][SST]

    const int tid  = threadIdx.x;
    const int m0   = blockIdx.y * 128;
    const int n0   = blockIdx.x * 128;
    const int lrow = tid >> 3;             // 0..31 (+ it*32)
    const int lc4  = tid & 7;              // float4 column within 32-k chunk

    const int lane = tid & 31, g = lane >> 2, t = lane & 3;
    const int wid  = tid >> 5, wm = wid >> 2, wn = wid & 3;

    float4 ra[4], rb[4];

    // ---- load chunk 0 ----
#pragma unroll
    for (int it = 0; it < 4; ++it) {
        const int row = lrow + it * 32;
        ra[it] = *(const float4*)(hs + (size_t)(m0 + row) * HID + lc4 * 4);
        rb[it] = *(const float4*)(w  + (size_t)(n0 + row) * HID + lc4 * 4);
    }
#pragma unroll
    for (int it = 0; it < 4; ++it) {
        const int row = lrow + it * 32;
        float4 va = make_float4(tf32r(ra[it].x), tf32r(ra[it].y),
                                tf32r(ra[it].z), tf32r(ra[it].w));
        float4 vb = make_float4(tf32r(rb[it].x), tf32r(rb[it].y),
                                tf32r(rb[it].z), tf32r(rb[it].w));
        *(float4*)(As + row * SST + lc4 * 4) = va;
        *(float4*)(Bs + row * SST + lc4 * 4) = vb;
    }
    __syncthreads();

    float c[4][4][4];
#pragma unroll
    for (int mi = 0; mi < 4; ++mi)
#pragma unroll
        for (int ni = 0; ni < 4; ++ni)
#pragma unroll
            for (int r = 0; r < 4; ++r) c[mi][ni][r] = 0.f;

    for (int ch = 0; ch < 32; ++ch) {
        const int p = ch & 1;
        if (ch < 31) {
            const int k0 = (ch + 1) * 32;
#pragma unroll
            for (int it = 0; it < 4; ++it) {
                const int row = lrow + it * 32;
                ra[it] = *(const float4*)(hs + (size_t)(m0 + row) * HID + k0 + lc4 * 4);
                rb[it] = *(const float4*)(w  + (size_t)(n0 + row) * HID + k0 + lc4 * 4);
            }
        }

        // ---- compute on buffer p ----
        const float* Ab = As + p * QG_BUF_FLOATS;
        const float* Bb = Bs + p * QG_BUF_FLOATS;
#pragma unroll
        for (int ks = 0; ks < 4; ++ks) {
            const int kc = ks * 8 + t;
            uint32_t a[4][4], b[4][2];
#pragma unroll
            for (int mi = 0; mi < 4; ++mi) {
                const float* ap = Ab + (wm * 64 + mi * 16 + g) * SST + kc;
                a[mi][0] = __float_as_uint(ap[0]);
                a[mi][1] = __float_as_uint(ap[8 * SST]);
                a[mi][2] = __float_as_uint(ap[4]);
                a[mi][3] = __float_as_uint(ap[8 * SST + 4]);
            }
#pragma unroll
            for (int ni = 0; ni < 4; ++ni) {
                const float* bp = Bb + (wn * 32 + ni * 8 + g) * SST + kc;
                b[ni][0] = __float_as_uint(bp[0]);
                b[ni][1] = __float_as_uint(bp[4]);
            }
#pragma unroll
            for (int mi = 0; mi < 4; ++mi)
#pragma unroll
                for (int ni = 0; ni < 4; ++ni)
                    mma16n8k8(c[mi][ni], a[mi], b[ni]);
        }

        if (ch < 31) {
            float* An = As + ((ch + 1) & 1) * QG_BUF_FLOATS;
            float* Bn = Bs + ((ch + 1) & 1) * QG_BUF_FLOATS;
#pragma unroll
            for (int it = 0; it < 4; ++it) {
                const int row = lrow + it * 32;
                float4 va = make_float4(tf32r(ra[it].x), tf32r(ra[it].y),
                                        tf32r(ra[it].z), tf32r(ra[it].w));
                float4 vb = make_float4(tf32r(rb[it].x), tf32r(rb[it].y),
                                        tf32r(rb[it].z), tf32r(rb[it].w));
                *(float4*)(An + row * SST + lc4 * 4) = va;
                *(float4*)(Bn + row * SST + lc4 * 4) = vb;
            }
        }
        __syncthreads();
    }

    // ---- epilogue: bias + scatter into head layout ----
    const int tsel = n0 >> 10;
    float* dst = (tsel == 0) ? g_Q : (tsel == 1) ? g_K : g_V;
#pragma unroll
    for (int mi = 0; mi < 4; ++mi) {
        const int m  = m0 + wm * 64 + mi * 16 + g;
        const int bb = m >> 10;
        const int s  = m & 1023;
#pragma unroll
        for (int ni = 0; ni < 4; ++ni) {
            const int gn  = n0 + wn * 32 + ni * 8 + t * 2;
            const int rem = gn & 1023;
            const int hh  = rem >> 6;
            const int dd  = rem & 63;
            const float2 bi = *(const float2*)(bias + gn);
            float* base = dst + ((size_t)(bb * NH + hh) * SEQ + s) * HD + dd;
            float2 v0 = make_float2(c[mi][ni][0] + bi.x, c[mi][ni][1] + bi.y);
            float2 v1 = make_float2(c[mi][ni][2] + bi.x, c[mi][ni][3] + bi.y);
            *(float2*)(base) = v0;
            *(float2*)(base + 8 * HD) = v1;
        }
    }
}

// ---------------------------------------------------------------------------
// Kernel 2: attention with relative_key_query bias, flash-style online
// softmax.  (unchanged — known correct)
// ---------------------------------------------------------------------------
#define QT_STRIDE 68
#define ET_STRIDE 129
#define PS_STRIDE 68
#define ATTN_SMEM_FLOATS (64*QT_STRIDE*2 + 64*ET_STRIDE + 64*64 + 64*PS_STRIDE)

__global__ __launch_bounds__(128) void attn_kernel(
    const float* __restrict__ emb,
    const float* __restrict__ mask,
    float* __restrict__ out)
{
    extern __shared__ __align__(16) float sm[];
    float* Qt = sm;                       // [64 dd][68]: Qt[dd*68 + i]
    float* Kt = Qt + 64 * QT_STRIDE;      // [64 dd][68]
    float* Et = Kt + 64 * QT_STRIDE;      // [64 dd][129]
    float* Vs = Et + 64 * ET_STRIDE;      // [64 j][64 dd]
    float* Ps = Vs + 64 * 64;             // [64 i][68]

    const int tid = threadIdx.x;
    const int ti  = tid >> 4;
    const int tj  = tid & 15;
    const int bh  = blockIdx.y;
    const int b   = bh >> 4;
    const int hh  = bh & 15;
    const int l0  = blockIdx.x * 64;

    const float* Qg = g_Q + ((size_t)bh * SEQ + l0) * HD;
    for (int idx = tid; idx < 64 * 64; idx += 128) {
        const int i = idx >> 6, dd = idx & 63;
        Qt[dd * QT_STRIDE + i] = Qg[idx];
    }

    float mrow[8], lsum[8], acc[8][4];
#pragma unroll
    for (int a = 0; a < 8; a++) {
        mrow[a] = -CUDART_INF_F; lsum[a] = 0.f;
#pragma unroll
        for (int c = 0; c < 4; c++) acc[a][c] = 0.f;
    }

    const int ibase = ti * 8 - tj * 4 + 60;

    for (int r0 = 0; r0 < SEQ; r0 += 64) {
        const float* Kg = g_K + ((size_t)bh * SEQ + r0) * HD;
        const float* Vg = g_V + ((size_t)bh * SEQ + r0) * HD;
        const int gb_ = l0 - r0 + 960;

        __syncthreads();
        for (int idx = tid; idx < 64 * 64; idx += 128) {
            const int i = idx >> 6, dd = idx & 63;
            Kt[dd * QT_STRIDE + i] = Kg[idx];
            Vs[idx] = Vg[idx];
        }
        for (int idx = tid; idx < 127 * 64; idx += 128) {
            const int ib = idx >> 6, dd = idx & 63;
            Et[dd * ET_STRIDE + ib] = emb[(size_t)(gb_ + ib) * HD + dd];
        }
        __syncthreads();

        float s[8][4];
#pragma unroll
        for (int a = 0; a < 8; a++)
#pragma unroll
            for (int c = 0; c < 4; c++) s[a][c] = 0.f;

#pragma unroll 4
        for (int dd = 0; dd < 64; dd++) {
            float q[8], k[4], e[11];
            const float* qr = &Qt[dd * QT_STRIDE + ti * 8];
            *(float4*)(q)     = *(const float4*)(qr);
            *(float4*)(q + 4) = *(const float4*)(qr + 4);
            *(float4*)(k)     = *(const float4*)&Kt[dd * QT_STRIDE + tj * 4];
            const float* er = &Et[dd * ET_STRIDE + ibase];
#pragma unroll
            for (int u = 0; u < 11; u++) e[u] = er[u];
#pragma unroll
            for (int a = 0; a < 8; a++)
#pragma unroll
                for (int c = 0; c < 4; c++)
                    s[a][c] += q[a] * k[c] + (q[a] + k[c]) * e[a - c + 3];
        }

        float mk[4];
#pragma unroll
        for (int c = 0; c < 4; c++) mk[c] = mask[b * SEQ + r0 + tj * 4 + c];
#pragma unroll
        for (int a = 0; a < 8; a++)
#pragma unroll
            for (int c = 0; c < 4; c++)
                s[a][c] = s[a][c] * 0.125f + mk[c];

#pragma unroll
        for (int a = 0; a < 8; a++) {
            float pm = fmaxf(fmaxf(s[a][0], s[a][1]), fmaxf(s[a][2], s[a][3]));
#pragma unroll
            for (int off = 8; off > 0; off >>= 1)
                pm = fmaxf(pm, __shfl_xor_sync(0xffffffffu, pm, off));
            const float mnew = fmaxf(mrow[a], pm);
            const float corr = __expf(mrow[a] - mnew);
            mrow[a] = mnew;
            float p4[4], ps = 0.f;
#pragma unroll
            for (int c = 0; c < 4; c++) { p4[c] = __expf(s[a][c] - mnew); ps += p4[c]; }
#pragma unroll
            for (int off = 8; off > 0; off >>= 1)
                ps += __shfl_xor_sync(0xffffffffu, ps, off);
            lsum[a] = lsum[a] * corr + ps;
#pragma unroll
            for (int c = 0; c < 4; c++) acc[a][c] *= corr;
            *(float4*)&Ps[(ti * 8 + a) * PS_STRIDE + tj * 4] =
                make_float4(p4[0], p4[1], p4[2], p4[3]);
        }
        __syncthreads();

#pragma unroll 2
        for (int j = 0; j < 64; j++) {
            const float4 v4 = *(const float4*)&Vs[j * 64 + tj * 4];
#pragma unroll
            for (int a = 0; a < 8; a++) {
                const float p = Ps[(ti * 8 + a) * PS_STRIDE + j];
                acc[a][0] += p * v4.x; acc[a][1] += p * v4.y;
                acc[a][2] += p * v4.z; acc[a][3] += p * v4.w;
            }
        }
    }

#pragma unroll
    for (int a = 0; a < 8; a++) {
        const float inv = 1.f / lsum[a];
        const int l = l0 + ti * 8 + a;
        const float4 v = make_float4(acc[a][0] * inv, acc[a][1] * inv,
                                     acc[a][2] * inv, acc[a][3] * inv);
        *(float4*)(out + (size_t)(b * SEQ + l) * HID + hh * HD + tj * 4) = v;
    }
}

// ---------------------------------------------------------------------------
extern "C" void kernel_launch(void* const* d_in, const int* in_sizes, int n_in,
                              void* d_out, int out_size)
{
    (void)in_sizes; (void)n_in; (void)out_size;
    const float* hs   = (const float*)d_in[0];
    const float* w    = (const float*)d_in[1];
    const float* bias = (const float*)d_in[2];
    const float* emb  = (const float*)d_in[3];
    const float* mask = (const float*)d_in[4];
    float* out = (float*)d_out;

    cudaFuncSetAttribute(qkv_gemm_mma,
                         cudaFuncAttributeMaxDynamicSharedMemorySize, QG_SMEM_B);
    qkv_gemm_mma<<<dim3(HID * 3 / 128, BATCH * SEQ / 128), 256, QG_SMEM_B>>>(hs, w, bias);

    const size_t smem = (size_t)ATTN_SMEM_FLOATS * sizeof(float);
    cudaFuncSetAttribute(attn_kernel,
                         cudaFuncAttributeMaxDynamicSharedMemorySize, (int)smem);
    attn_kernel<<<dim3(SEQ / 64, BATCH * NH), 128, smem>>>(emb, mask, out);
}

// round 5
// speedup vs baseline: 1.4765x; 1.1419x over previous
#include <cuda_runtime.h>
#include <math_constants.h>
#include <cstdint>

#define NH    16
#define HD    64
#define SEQ   1024
#define BATCH 4
#define HID   1024

// scratch: Q/K/V in [b, h, s, d] layout (16 MB each)
__device__ float g_Q[BATCH * NH * SEQ * HD];
__device__ float g_K[BATCH * NH * SEQ * HD];
__device__ float g_V[BATCH * NH * SEQ * HD];

// ===========================================================================
// packed fp32x2 helpers (sm_100-family PTX; full fp32 precision, 2 lanes/instr)
// ===========================================================================
typedef unsigned long long u64;

__device__ __forceinline__ u64 f2pack(float lo, float hi) {
    u64 r; asm("mov.b64 %0, {%1, %2};" : "=l"(r) : "f"(lo), "f"(hi)); return r;
}
__device__ __forceinline__ void f2unpack(u64 v, float& lo, float& hi) {
    asm("mov.b64 {%0, %1}, %2;" : "=f"(lo), "=f"(hi) : "l"(v));
}
__device__ __forceinline__ u64 f2add(u64 a, u64 b) {
    u64 r; asm("add.rn.f32x2 %0, %1, %2;" : "=l"(r) : "l"(a), "l"(b)); return r;
}
__device__ __forceinline__ u64 f2mul(u64 a, u64 b) {
    u64 r; asm("mul.rn.f32x2 %0, %1, %2;" : "=l"(r) : "l"(a), "l"(b)); return r;
}
__device__ __forceinline__ u64 f2fma(u64 a, u64 b, u64 c) {
    u64 r; asm("fma.rn.f32x2 %0, %1, %2, %3;" : "=l"(r) : "l"(a), "l"(b), "l"(c)); return r;
}

// ===========================================================================
// Kernel 1: fused QKV projection via mma.sync tf32 (unchanged from R4 — WIN)
// ===========================================================================
#define SST 36
#define QG_BUF_FLOATS (128 * SST)
#define QG_SMEM_B (4 * QG_BUF_FLOATS * 4)

__device__ __forceinline__ float tf32r(float x) {
    uint32_t u;
    asm("cvt.rna.tf32.f32 %0, %1;" : "=r"(u) : "f"(x));
    return __uint_as_float(u);
}

__device__ __forceinline__ void mma16n8k8(float c[4], const uint32_t a[4],
                                          const uint32_t b[2]) {
    asm volatile(
        "mma.sync.aligned.m16n8k8.row.col.f32.tf32.tf32.f32 "
        "{%0,%1,%2,%3}, {%4,%5,%6,%7}, {%8,%9}, {%0,%1,%2,%3};"
        : "+f"(c[0]), "+f"(c[1]), "+f"(c[2]), "+f"(c[3])
        : "r"(a[0]), "r"(a[1]), "r"(a[2]), "r"(a[3]), "r"(b[0]), "r"(b[1]));
}

__global__ __launch_bounds__(256) void qkv_gemm_mma(
    const float* __restrict__ hs,
    const float* __restrict__ w,
    const float* __restrict__ bias)
{
    extern __shared__ __align__(16) float sm[];
    float* As = sm;
    float* Bs = sm + 2 * QG_BUF_FLOATS;

    const int tid  = threadIdx.x;
    const int m0   = blockIdx.y * 128;
    const int n0   = blockIdx.x * 128;
    const int lrow = tid >> 3;
    const int lc4  = tid & 7;

    const int lane = tid & 31, g = lane >> 2, t = lane & 3;
    const int wid  = tid >> 5, wm = wid >> 2, wn = wid & 3;

    float4 ra[4], rb[4];

#pragma unroll
    for (int it = 0; it < 4; ++it) {
        const int row = lrow + it * 32;
        ra[it] = *(const float4*)(hs + (size_t)(m0 + row) * HID + lc4 * 4);
        rb[it] = *(const float4*)(w  + (size_t)(n0 + row) * HID + lc4 * 4);
    }
#pragma unroll
    for (int it = 0; it < 4; ++it) {
        const int row = lrow + it * 32;
        float4 va = make_float4(tf32r(ra[it].x), tf32r(ra[it].y),
                                tf32r(ra[it].z), tf32r(ra[it].w));
        float4 vb = make_float4(tf32r(rb[it].x), tf32r(rb[it].y),
                                tf32r(rb[it].z), tf32r(rb[it].w));
        *(float4*)(As + row * SST + lc4 * 4) = va;
        *(float4*)(Bs + row * SST + lc4 * 4) = vb;
    }
    __syncthreads();

    float c[4][4][4];
#pragma unroll
    for (int mi = 0; mi < 4; ++mi)
#pragma unroll
        for (int ni = 0; ni < 4; ++ni)
#pragma unroll
            for (int r = 0; r < 4; ++r) c[mi][ni][r] = 0.f;

    for (int ch = 0; ch < 32; ++ch) {
        const int p = ch & 1;
        if (ch < 31) {
            const int k0 = (ch + 1) * 32;
#pragma unroll
            for (int it = 0; it < 4; ++it) {
                const int row = lrow + it * 32;
                ra[it] = *(const float4*)(hs + (size_t)(m0 + row) * HID + k0 + lc4 * 4);
                rb[it] = *(const float4*)(w  + (size_t)(n0 + row) * HID + k0 + lc4 * 4);
            }
        }

        const float* Ab = As + p * QG_BUF_FLOATS;
        const float* Bb = Bs + p * QG_BUF_FLOATS;
#pragma unroll
        for (int ks = 0; ks < 4; ++ks) {
            const int kc = ks * 8 + t;
            uint32_t a[4][4], b[4][2];
#pragma unroll
            for (int mi = 0; mi < 4; ++mi) {
                const float* ap = Ab + (wm * 64 + mi * 16 + g) * SST + kc;
                a[mi][0] = __float_as_uint(ap[0]);
                a[mi][1] = __float_as_uint(ap[8 * SST]);
                a[mi][2] = __float_as_uint(ap[4]);
                a[mi][3] = __float_as_uint(ap[8 * SST + 4]);
            }
#pragma unroll
            for (int ni = 0; ni < 4; ++ni) {
                const float* bp = Bb + (wn * 32 + ni * 8 + g) * SST + kc;
                b[ni][0] = __float_as_uint(bp[0]);
                b[ni][1] = __float_as_uint(bp[4]);
            }
#pragma unroll
            for (int mi = 0; mi < 4; ++mi)
#pragma unroll
                for (int ni = 0; ni < 4; ++ni)
                    mma16n8k8(c[mi][ni], a[mi], b[ni]);
        }

        if (ch < 31) {
            float* An = As + ((ch + 1) & 1) * QG_BUF_FLOATS;
            float* Bn = Bs + ((ch + 1) & 1) * QG_BUF_FLOATS;
#pragma unroll
            for (int it = 0; it < 4; ++it) {
                const int row = lrow + it * 32;
                float4 va = make_float4(tf32r(ra[it].x), tf32r(ra[it].y),
                                        tf32r(ra[it].z), tf32r(ra[it].w));
                float4 vb = make_float4(tf32r(rb[it].x), tf32r(rb[it].y),
                                        tf32r(rb[it].z), tf32r(rb[it].w));
                *(float4*)(An + row * SST + lc4 * 4) = va;
                *(float4*)(Bn + row * SST + lc4 * 4) = vb;
            }
        }
        __syncthreads();
    }

    const int tsel = n0 >> 10;
    float* dst = (tsel == 0) ? g_Q : (tsel == 1) ? g_K : g_V;
#pragma unroll
    for (int mi = 0; mi < 4; ++mi) {
        const int m  = m0 + wm * 64 + mi * 16 + g;
        const int bb = m >> 10;
        const int s  = m & 1023;
#pragma unroll
        for (int ni = 0; ni < 4; ++ni) {
            const int gn  = n0 + wn * 32 + ni * 8 + t * 2;
            const int rem = gn & 1023;
            const int hh  = rem >> 6;
            const int dd  = rem & 63;
            const float2 bi = *(const float2*)(bias + gn);
            float* base = dst + ((size_t)(bb * NH + hh) * SEQ + s) * HD + dd;
            float2 v0 = make_float2(c[mi][ni][0] + bi.x, c[mi][ni][1] + bi.y);
            float2 v1 = make_float2(c[mi][ni][2] + bi.x, c[mi][ni][3] + bi.y);
            *(float2*)(base) = v0;
            *(float2*)(base + 8 * HD) = v1;
        }
    }
}

// ---------------------------------------------------------------------------
// Kernel 2: attention, flash-style online softmax, packed f32x2 inner loops.
// Score pairs over rows (q-pairs free from ulonglong2 loads); e band
// vectorized (ET_STRIDE=132 keeps float4 alignment: ibase % 4 == 0).
// ---------------------------------------------------------------------------
#define QT_STRIDE 68
#define ET_STRIDE 132
#define PS_STRIDE 68
#define ATTN_SMEM_FLOATS (64*QT_STRIDE*2 + 64*ET_STRIDE + 64*64 + 64*PS_STRIDE)

__global__ __launch_bounds__(128) void attn_kernel(
    const float* __restrict__ emb,
    const float* __restrict__ mask,
    float* __restrict__ out)
{
    extern __shared__ __align__(16) float sm2[];
    float* Qt = sm2;                      // [64 dd][68]: Qt[dd*68 + i]
    float* Kt = Qt + 64 * QT_STRIDE;      // [64 dd][68]
    float* Et = Kt + 64 * QT_STRIDE;      // [64 dd][132]
    float* Vs = Et + 64 * ET_STRIDE;      // [64 j][64 dd]
    float* Ps = Vs + 64 * 64;             // [64 i][68]

    const int tid = threadIdx.x;
    const int ti  = tid >> 4;   // 0..7  rows i0 = ti*8
    const int tj  = tid & 15;   // 0..15 cols j0 = tj*4
    const int bh  = blockIdx.y;
    const int b   = bh >> 4;
    const int hh  = bh & 15;
    const int l0  = blockIdx.x * 64;

    const float* Qg = g_Q + ((size_t)bh * SEQ + l0) * HD;
    for (int idx = tid; idx < 64 * 64; idx += 128) {
        const int i = idx >> 6, dd = idx & 63;
        Qt[dd * QT_STRIDE + i] = Qg[idx];
    }

    float mrow[8], lsum[8];
    u64 acc2[8][2];
#pragma unroll
    for (int a = 0; a < 8; a++) {
        mrow[a] = -CUDART_INF_F; lsum[a] = 0.f;
        acc2[a][0] = 0ull; acc2[a][1] = 0ull;
    }

    const int ibase = ti * 8 - tj * 4 + 60;   // %4 == 0 -> float4-aligned e loads

    for (int r0 = 0; r0 < SEQ; r0 += 64) {
        const float* Kg = g_K + ((size_t)bh * SEQ + r0) * HD;
        const float* Vg = g_V + ((size_t)bh * SEQ + r0) * HD;
        const int gb_ = l0 - r0 + 960;

        __syncthreads();
        for (int idx = tid; idx < 64 * 64; idx += 128) {
            const int i = idx >> 6, dd = idx & 63;
            Kt[dd * QT_STRIDE + i] = Kg[idx];
            Vs[idx] = Vg[idx];
        }
        for (int idx = tid; idx < 127 * 64; idx += 128) {
            const int ib = idx >> 6, dd = idx & 63;
            Et[dd * ET_STRIDE + ib] = emb[(size_t)(gb_ + ib) * HD + dd];
        }
        __syncthreads();

        // ---- score tile: packed over row pairs ----
        u64 s2[4][4];
#pragma unroll
        for (int a2 = 0; a2 < 4; a2++)
#pragma unroll
            for (int c = 0; c < 4; c++) s2[a2][c] = 0ull;

#pragma unroll 2
        for (int dd = 0; dd < 64; dd++) {
            const float* qr = &Qt[dd * QT_STRIDE + ti * 8];
            const ulonglong2 qA = *(const ulonglong2*)(qr);       // (q0,q1),(q2,q3)
            const ulonglong2 qB = *(const ulonglong2*)(qr + 4);   // (q4,q5),(q6,q7)
            u64 qp[4] = {qA.x, qA.y, qB.x, qB.y};

            const float4 kv = *(const float4*)&Kt[dd * QT_STRIDE + tj * 4];
            u64 kb[4];
            kb[0] = f2pack(kv.x, kv.x); kb[1] = f2pack(kv.y, kv.y);
            kb[2] = f2pack(kv.z, kv.z); kb[3] = f2pack(kv.w, kv.w);

            const float* er = &Et[dd * ET_STRIDE + ibase];
            const float4 e0 = *(const float4*)(er);
            const float4 e1 = *(const float4*)(er + 4);
            const float4 e2 = *(const float4*)(er + 8);
            const float e[12] = {e0.x, e0.y, e0.z, e0.w,
                                 e1.x, e1.y, e1.z, e1.w,
                                 e2.x, e2.y, e2.z, e2.w};
            u64 P[10];
#pragma unroll
            for (int m = 0; m < 10; m++) P[m] = f2pack(e[m], e[m + 1]);

#pragma unroll
            for (int a2 = 0; a2 < 4; a2++)
#pragma unroll
                for (int c = 0; c < 4; c++) {
                    s2[a2][c] = f2fma(qp[a2], kb[c], s2[a2][c]);
                    const u64 t = f2add(qp[a2], kb[c]);
                    s2[a2][c] = f2fma(t, P[2 * a2 - c + 3], s2[a2][c]);
                }
        }

        // ---- unpack, scale + mask ----
        float s[8][4];
#pragma unroll
        for (int a2 = 0; a2 < 4; a2++)
#pragma unroll
            for (int c = 0; c < 4; c++)
                f2unpack(s2[a2][c], s[2 * a2][c], s[2 * a2 + 1][c]);

        float mk[4];
#pragma unroll
        for (int c = 0; c < 4; c++) mk[c] = mask[b * SEQ + r0 + tj * 4 + c];
#pragma unroll
        for (int a = 0; a < 8; a++)
#pragma unroll
            for (int c = 0; c < 4; c++)
                s[a][c] = s[a][c] * 0.125f + mk[c];

        // ---- online softmax (row reduce over 16 tj lanes) ----
#pragma unroll
        for (int a = 0; a < 8; a++) {
            float pm = fmaxf(fmaxf(s[a][0], s[a][1]), fmaxf(s[a][2], s[a][3]));
#pragma unroll
            for (int off = 8; off > 0; off >>= 1)
                pm = fmaxf(pm, __shfl_xor_sync(0xffffffffu, pm, off));
            const float mnew = fmaxf(mrow[a], pm);
            const float corr = __expf(mrow[a] - mnew);
            mrow[a] = mnew;
            float p4[4], ps = 0.f;
#pragma unroll
            for (int c = 0; c < 4; c++) { p4[c] = __expf(s[a][c] - mnew); ps += p4[c]; }
#pragma unroll
            for (int off = 8; off > 0; off >>= 1)
                ps += __shfl_xor_sync(0xffffffffu, ps, off);
            lsum[a] = lsum[a] * corr + ps;
            const u64 cc = f2pack(corr, corr);
            acc2[a][0] = f2mul(acc2[a][0], cc);
            acc2[a][1] = f2mul(acc2[a][1], cc);
            *(float4*)&Ps[(ti * 8 + a) * PS_STRIDE + tj * 4] =
                make_float4(p4[0], p4[1], p4[2], p4[3]);
        }
        __syncthreads();

        // ---- P @ V (packed over column pairs; v-pairs free via ulonglong2) ----
#pragma unroll 2
        for (int j = 0; j < 64; j++) {
            const ulonglong2 vv = *(const ulonglong2*)&Vs[j * 64 + tj * 4];
#pragma unroll
            for (int a = 0; a < 8; a++) {
                const float p = Ps[(ti * 8 + a) * PS_STRIDE + j];
                const u64 pb = f2pack(p, p);
                acc2[a][0] = f2fma(pb, vv.x, acc2[a][0]);
                acc2[a][1] = f2fma(pb, vv.y, acc2[a][1]);
            }
        }
    }

    // ---- write context ----
#pragma unroll
    for (int a = 0; a < 8; a++) {
        const float inv = 1.f / lsum[a];
        float x, y, z, w;
        f2unpack(acc2[a][0], x, y);
        f2unpack(acc2[a][1], z, w);
        const int l = l0 + ti * 8 + a;
        const float4 v = make_float4(x * inv, y * inv, z * inv, w * inv);
        *(float4*)(out + (size_t)(b * SEQ + l) * HID + hh * HD + tj * 4) = v;
    }
}

// ---------------------------------------------------------------------------
extern "C" void kernel_launch(void* const* d_in, const int* in_sizes, int n_in,
                              void* d_out, int out_size)
{
    (void)in_sizes; (void)n_in; (void)out_size;
    const float* hs   = (const float*)d_in[0];
    const float* w    = (const float*)d_in[1];
    const float* bias = (const float*)d_in[2];
    const float* emb  = (const float*)d_in[3];
    const float* mask = (const float*)d_in[4];
    float* out = (float*)d_out;

    cudaFuncSetAttribute(qkv_gemm_mma,
                         cudaFuncAttributeMaxDynamicSharedMemorySize, QG_SMEM_B);
    qkv_gemm_mma<<<dim3(HID * 3 / 128, BATCH * SEQ / 128), 256, QG_SMEM_B>>>(hs, w, bias);

    const size_t smem = (size_t)ATTN_SMEM_FLOATS * sizeof(float);
    cudaFuncSetAttribute(attn_kernel,
                         cudaFuncAttributeMaxDynamicSharedMemorySize, (int)smem);
    attn_kernel<<<dim3(SEQ / 64, BATCH * NH), 128, smem>>>(emb, mask, out);
}

// round 6
// speedup vs baseline: 1.6264x; 1.1015x over previous
#include <cuda_runtime.h>
#include <math_constants.h>
#include <cstdint>

#define NH    16
#define HD    64
#define SEQ   1024
#define BATCH 4
#define HID   1024

// scratch: Q/K/V in [b, h, s, d] layout (16 MB each)
__device__ float g_Q[BATCH * NH * SEQ * HD];
__device__ float g_K[BATCH * NH * SEQ * HD];
__device__ float g_V[BATCH * NH * SEQ * HD];

// ===========================================================================
// packed fp32x2 helpers
// ===========================================================================
typedef unsigned long long u64;

__device__ __forceinline__ u64 f2pack(float lo, float hi) {
    u64 r; asm("mov.b64 %0, {%1, %2};" : "=l"(r) : "f"(lo), "f"(hi)); return r;
}
__device__ __forceinline__ void f2unpack(u64 v, float& lo, float& hi) {
    asm("mov.b64 {%0, %1}, %2;" : "=f"(lo), "=f"(hi) : "l"(v));
}
__device__ __forceinline__ u64 f2add(u64 a, u64 b) {
    u64 r; asm("add.rn.f32x2 %0, %1, %2;" : "=l"(r) : "l"(a), "l"(b)); return r;
}
__device__ __forceinline__ u64 f2mul(u64 a, u64 b) {
    u64 r; asm("mul.rn.f32x2 %0, %1, %2;" : "=l"(r) : "l"(a), "l"(b)); return r;
}
__device__ __forceinline__ u64 f2fma(u64 a, u64 b, u64 c) {
    u64 r; asm("fma.rn.f32x2 %0, %1, %2, %3;" : "=l"(r) : "l"(a), "l"(b), "l"(c)); return r;
}

// ===========================================================================
// Kernel 1: fused QKV projection via mma.sync tf32 (unchanged — WIN from R4)
// ===========================================================================
#define SST 36
#define QG_BUF_FLOATS (128 * SST)
#define QG_SMEM_B (4 * QG_BUF_FLOATS * 4)

__device__ __forceinline__ float tf32r(float x) {
    uint32_t u;
    asm("cvt.rna.tf32.f32 %0, %1;" : "=r"(u) : "f"(x));
    return __uint_as_float(u);
}

__device__ __forceinline__ void mma16n8k8(float c[4], const uint32_t a[4],
                                          const uint32_t b[2]) {
    asm volatile(
        "mma.sync.aligned.m16n8k8.row.col.f32.tf32.tf32.f32 "
        "{%0,%1,%2,%3}, {%4,%5,%6,%7}, {%8,%9}, {%0,%1,%2,%3};"
        : "+f"(c[0]), "+f"(c[1]), "+f"(c[2]), "+f"(c[3])
        : "r"(a[0]), "r"(a[1]), "r"(a[2]), "r"(a[3]), "r"(b[0]), "r"(b[1]));
}

__global__ __launch_bounds__(256) void qkv_gemm_mma(
    const float* __restrict__ hs,
    const float* __restrict__ w,
    const float* __restrict__ bias)
{
    extern __shared__ __align__(16) float sm[];
    float* As = sm;
    float* Bs = sm + 2 * QG_BUF_FLOATS;

    const int tid  = threadIdx.x;
    const int m0   = blockIdx.y * 128;
    const int n0   = blockIdx.x * 128;
    const int lrow = tid >> 3;
    const int lc4  = tid & 7;

    const int lane = tid & 31, g = lane >> 2, t = lane & 3;
    const int wid  = tid >> 5, wm = wid >> 2, wn = wid & 3;

    float4 ra[4], rb[4];

#pragma unroll
    for (int it = 0; it < 4; ++it) {
        const int row = lrow + it * 32;
        ra[it] = *(const float4*)(hs + (size_t)(m0 + row) * HID + lc4 * 4);
        rb[it] = *(const float4*)(w  + (size_t)(n0 + row) * HID + lc4 * 4);
    }
#pragma unroll
    for (int it = 0; it < 4; ++it) {
        const int row = lrow + it * 32;
        float4 va = make_float4(tf32r(ra[it].x), tf32r(ra[it].y),
                                tf32r(ra[it].z), tf32r(ra[it].w));
        float4 vb = make_float4(tf32r(rb[it].x), tf32r(rb[it].y),
                                tf32r(rb[it].z), tf32r(rb[it].w));
        *(float4*)(As + row * SST + lc4 * 4) = va;
        *(float4*)(Bs + row * SST + lc4 * 4) = vb;
    }
    __syncthreads();

    float c[4][4][4];
#pragma unroll
    for (int mi = 0; mi < 4; ++mi)
#pragma unroll
        for (int ni = 0; ni < 4; ++ni)
#pragma unroll
            for (int r = 0; r < 4; ++r) c[mi][ni][r] = 0.f;

    for (int ch = 0; ch < 32; ++ch) {
        const int p = ch & 1;
        if (ch < 31) {
            const int k0 = (ch + 1) * 32;
#pragma unroll
            for (int it = 0; it < 4; ++it) {
                const int row = lrow + it * 32;
                ra[it] = *(const float4*)(hs + (size_t)(m0 + row) * HID + k0 + lc4 * 4);
                rb[it] = *(const float4*)(w  + (size_t)(n0 + row) * HID + k0 + lc4 * 4);
            }
        }

        const float* Ab = As + p * QG_BUF_FLOATS;
        const float* Bb = Bs + p * QG_BUF_FLOATS;
#pragma unroll
        for (int ks = 0; ks < 4; ++ks) {
            const int kc = ks * 8 + t;
            uint32_t a[4][4], b[4][2];
#pragma unroll
            for (int mi = 0; mi < 4; ++mi) {
                const float* ap = Ab + (wm * 64 + mi * 16 + g) * SST + kc;
                a[mi][0] = __float_as_uint(ap[0]);
                a[mi][1] = __float_as_uint(ap[8 * SST]);
                a[mi][2] = __float_as_uint(ap[4]);
                a[mi][3] = __float_as_uint(ap[8 * SST + 4]);
            }
#pragma unroll
            for (int ni = 0; ni < 4; ++ni) {
                const float* bp = Bb + (wn * 32 + ni * 8 + g) * SST + kc;
                b[ni][0] = __float_as_uint(bp[0]);
                b[ni][1] = __float_as_uint(bp[4]);
            }
#pragma unroll
            for (int mi = 0; mi < 4; ++mi)
#pragma unroll
                for (int ni = 0; ni < 4; ++ni)
                    mma16n8k8(c[mi][ni], a[mi], b[ni]);
        }

        if (ch < 31) {
            float* An = As + ((ch + 1) & 1) * QG_BUF_FLOATS;
            float* Bn = Bs + ((ch + 1) & 1) * QG_BUF_FLOATS;
#pragma unroll
            for (int it = 0; it < 4; ++it) {
                const int row = lrow + it * 32;
                float4 va = make_float4(tf32r(ra[it].x), tf32r(ra[it].y),
                                        tf32r(ra[it].z), tf32r(ra[it].w));
                float4 vb = make_float4(tf32r(rb[it].x), tf32r(rb[it].y),
                                        tf32r(rb[it].z), tf32r(rb[it].w));
                *(float4*)(An + row * SST + lc4 * 4) = va;
                *(float4*)(Bn + row * SST + lc4 * 4) = vb;
            }
        }
        __syncthreads();
    }

    const int tsel = n0 >> 10;
    float* dst = (tsel == 0) ? g_Q : (tsel == 1) ? g_K : g_V;
#pragma unroll
    for (int mi = 0; mi < 4; ++mi) {
        const int m  = m0 + wm * 64 + mi * 16 + g;
        const int bb = m >> 10;
        const int s  = m & 1023;
#pragma unroll
        for (int ni = 0; ni < 4; ++ni) {
            const int gn  = n0 + wn * 32 + ni * 8 + t * 2;
            const int rem = gn & 1023;
            const int hh  = rem >> 6;
            const int dd  = rem & 63;
            const float2 bi = *(const float2*)(bias + gn);
            float* base = dst + ((size_t)(bb * NH + hh) * SEQ + s) * HD + dd;
            float2 v0 = make_float2(c[mi][ni][0] + bi.x, c[mi][ni][1] + bi.y);
            float2 v1 = make_float2(c[mi][ni][2] + bi.x, c[mi][ni][3] + bi.y);
            *(float2*)(base) = v0;
            *(float2*)(base + 8 * HD) = v1;
        }
    }
}

// ---------------------------------------------------------------------------
// Kernel 2: attention, 256 threads (4x4 microtile), f32x2 packed math,
// P stored to smem as pre-packed row-pair u64s (no per-j p-packs in PV).
// ---------------------------------------------------------------------------
#define QT_STRIDE 68
#define ET_STRIDE 132
#define PP_STRIDE 33   // u64 units per j-row
#define ATTN_SMEM_FLOATS (64*QT_STRIDE*2 + 64*ET_STRIDE + 64*64 + 64*PP_STRIDE*2)

__global__ __launch_bounds__(256) void attn_kernel(
    const float* __restrict__ emb,
    const float* __restrict__ mask,
    float* __restrict__ out)
{
    extern __shared__ __align__(16) float sm2[];
    float* Qt  = sm2;                      // [64 dd][68]
    float* Kt  = Qt + 64 * QT_STRIDE;      // [64 dd][68]
    float* Et  = Kt + 64 * QT_STRIDE;      // [64 dd][132]
    float* Vs  = Et + 64 * ET_STRIDE;      // [64 j][64 dd]
    u64*   Pp  = (u64*)(Vs + 64 * 64);     // [64 j][33]

    const int tid = threadIdx.x;
    const int ti  = tid >> 4;   // 0..15 -> rows i0 = ti*4
    const int tj  = tid & 15;   // 0..15 -> cols j0 = tj*4
    const int bh  = blockIdx.y;
    const int b   = bh >> 4;
    const int hh  = bh & 15;
    const int l0  = blockIdx.x * 64;

    const float* Qg = g_Q + ((size_t)bh * SEQ + l0) * HD;
    for (int idx = tid; idx < 64 * 64; idx += 256) {
        const int i = idx >> 6, dd = idx & 63;
        Qt[dd * QT_STRIDE + i] = Qg[idx];
    }

    float mrow[4], lsum[4];
    u64 acc[2][4];
#pragma unroll
    for (int a = 0; a < 4; a++) { mrow[a] = -CUDART_INF_F; lsum[a] = 0.f; }
#pragma unroll
    for (int a2 = 0; a2 < 2; a2++)
#pragma unroll
        for (int c = 0; c < 4; c++) acc[a2][c] = 0ull;

    const int ibase = ti * 4 - tj * 4 + 60;

    for (int r0 = 0; r0 < SEQ; r0 += 64) {
        const float* Kg = g_K + ((size_t)bh * SEQ + r0) * HD;
        const float* Vg = g_V + ((size_t)bh * SEQ + r0) * HD;
        const int gb_ = l0 - r0 + 960;

        __syncthreads();
        for (int idx = tid; idx < 64 * 64; idx += 256) {
            const int i = idx >> 6, dd = idx & 63;
            Kt[dd * QT_STRIDE + i] = Kg[idx];
            Vs[idx] = Vg[idx];
        }
        for (int idx = tid; idx < 127 * 64; idx += 256) {
            const int ib = idx >> 6, dd = idx & 63;
            Et[dd * ET_STRIDE + ib] = emb[(size_t)(gb_ + ib) * HD + dd];
        }
        __syncthreads();

        // ---- score tile ----
        u64 s2[2][4];
#pragma unroll
        for (int a2 = 0; a2 < 2; a2++)
#pragma unroll
            for (int c = 0; c < 4; c++) s2[a2][c] = 0ull;

#pragma unroll 2
        for (int dd = 0; dd < 64; dd++) {
            const ulonglong2 qA = *(const ulonglong2*)&Qt[dd * QT_STRIDE + ti * 4];
            const u64 qp[2] = {qA.x, qA.y};

            const float4 kv = *(const float4*)&Kt[dd * QT_STRIDE + tj * 4];
            u64 kb[4];
            kb[0] = f2pack(kv.x, kv.x); kb[1] = f2pack(kv.y, kv.y);
            kb[2] = f2pack(kv.z, kv.z); kb[3] = f2pack(kv.w, kv.w);

            const float* er = &Et[dd * ET_STRIDE + ibase];
            const float4 e0 = *(const float4*)(er);
            const float4 e1 = *(const float4*)(er + 4);
            const float e[8] = {e0.x, e0.y, e0.z, e0.w, e1.x, e1.y, e1.z, e1.w};
            u64 P[6];
#pragma unroll
            for (int m = 0; m < 6; m++) P[m] = f2pack(e[m], e[m + 1]);

#pragma unroll
            for (int a2 = 0; a2 < 2; a2++)
#pragma unroll
                for (int c = 0; c < 4; c++) {
                    s2[a2][c] = f2fma(qp[a2], kb[c], s2[a2][c]);
                    const u64 t = f2add(qp[a2], kb[c]);
                    s2[a2][c] = f2fma(t, P[2 * a2 - c + 3], s2[a2][c]);
                }
        }

        // ---- unpack, scale + mask ----
        float s[4][4];
#pragma unroll
        for (int a2 = 0; a2 < 2; a2++)
#pragma unroll
            for (int c = 0; c < 4; c++)
                f2unpack(s2[a2][c], s[2 * a2][c], s[2 * a2 + 1][c]);

        float mk[4];
#pragma unroll
        for (int c = 0; c < 4; c++) mk[c] = mask[b * SEQ + r0 + tj * 4 + c];
#pragma unroll
        for (int a = 0; a < 4; a++)
#pragma unroll
            for (int c = 0; c < 4; c++)
                s[a][c] = s[a][c] * 0.125f + mk[c];

        // ---- online softmax ----
        float pall[4][4], corr[4];
#pragma unroll
        for (int a = 0; a < 4; a++) {
            float pm = fmaxf(fmaxf(s[a][0], s[a][1]), fmaxf(s[a][2], s[a][3]));
#pragma unroll
            for (int off = 8; off > 0; off >>= 1)
                pm = fmaxf(pm, __shfl_xor_sync(0xffffffffu, pm, off));
            const float mnew = fmaxf(mrow[a], pm);
            corr[a] = __expf(mrow[a] - mnew);
            mrow[a] = mnew;
            float ps = 0.f;
#pragma unroll
            for (int c = 0; c < 4; c++) { pall[a][c] = __expf(s[a][c] - mnew); ps += pall[a][c]; }
#pragma unroll
            for (int off = 8; off > 0; off >>= 1)
                ps += __shfl_xor_sync(0xffffffffu, ps, off);
            lsum[a] = lsum[a] * corr[a] + ps;
        }
#pragma unroll
        for (int a2 = 0; a2 < 2; a2++) {
            const u64 cc = f2pack(corr[2 * a2], corr[2 * a2 + 1]);
#pragma unroll
            for (int c = 0; c < 4; c++) acc[a2][c] = f2mul(acc[a2][c], cc);
#pragma unroll
            for (int c = 0; c < 4; c++)
                Pp[(tj * 4 + c) * PP_STRIDE + ti * 2 + a2] =
                    f2pack(pall[2 * a2][c], pall[2 * a2 + 1][c]);
        }
        __syncthreads();

        // ---- P @ V ----
#pragma unroll 2
        for (int j = 0; j < 64; j++) {
            const float4 vv = *(const float4*)&Vs[j * 64 + tj * 4];
            u64 vb[4];
            vb[0] = f2pack(vv.x, vv.x); vb[1] = f2pack(vv.y, vv.y);
            vb[2] = f2pack(vv.z, vv.z); vb[3] = f2pack(vv.w, vv.w);
            const u64 pp0 = Pp[j * PP_STRIDE + ti * 2 + 0];
            const u64 pp1 = Pp[j * PP_STRIDE + ti * 2 + 1];
#pragma unroll
            for (int c = 0; c < 4; c++) {
                acc[0][c] = f2fma(pp0, vb[c], acc[0][c]);
                acc[1][c] = f2fma(pp1, vb[c], acc[1][c]);
            }
        }
    }

    // ---- write context ----
#pragma unroll
    for (int a2 = 0; a2 < 2; a2++) {
        float lo[4], hi[4];
#pragma unroll
        for (int c = 0; c < 4; c++) f2unpack(acc[a2][c], lo[c], hi[c]);
        const float inv0 = 1.f / lsum[2 * a2];
        const float inv1 = 1.f / lsum[2 * a2 + 1];
        const int l = l0 + ti * 4 + 2 * a2;
        *(float4*)(out + (size_t)(b * SEQ + l) * HID + hh * HD + tj * 4) =
            make_float4(lo[0] * inv0, lo[1] * inv0, lo[2] * inv0, lo[3] * inv0);
        *(float4*)(out + (size_t)(b * SEQ + l + 1) * HID + hh * HD + tj * 4) =
            make_float4(hi[0] * inv1, hi[1] * inv1, hi[2] * inv1, hi[3] * inv1);
    }
}

// ---------------------------------------------------------------------------
extern "C" void kernel_launch(void* const* d_in, const int* in_sizes, int n_in,
                              void* d_out, int out_size)
{
    (void)in_sizes; (void)n_in; (void)out_size;
    const float* hs   = (const float*)d_in[0];
    const float* w    = (const float*)d_in[1];
    const float* bias = (const float*)d_in[2];
    const float* emb  = (const float*)d_in[3];
    const float* mask = (const float*)d_in[4];
    float* out = (float*)d_out;

    cudaFuncSetAttribute(qkv_gemm_mma,
                         cudaFuncAttributeMaxDynamicSharedMemorySize, QG_SMEM_B);
    qkv_gemm_mma<<<dim3(HID * 3 / 128, BATCH * SEQ / 128), 256, QG_SMEM_B>>>(hs, w, bias);

    const size_t smem = (size_t)ATTN_SMEM_FLOATS * sizeof(float);
    cudaFuncSetAttribute(attn_kernel,
                         cudaFuncAttributeMaxDynamicSharedMemorySize, (int)smem);
    attn_kernel<<<dim3(SEQ / 64, BATCH * NH), 256, smem>>>(emb, mask, out);
}